// round 3
// baseline (speedup 1.0000x reference)
#include <cuda_runtime.h>

// Problem constants (shapes fixed by the dataset)
#define FIN   256
#define FOUT  128
#define N_MAX 100000

// 51.2 MB scratch for h = x @ W   (allocation-free: __device__ global)
__device__ float g_h[(size_t)N_MAX * FOUT];

// ---------------------------------------------------------------------------
// Kernel 0: zero the output accumulator (d_out is poisoned / stale on replay)
// ---------------------------------------------------------------------------
__global__ void zero_kernel(float4* __restrict__ out, int n4) {
    int i = blockIdx.x * blockDim.x + threadIdx.x;
    if (i < n4) out[i] = make_float4(0.f, 0.f, 0.f, 0.f);
}

// ---------------------------------------------------------------------------
// Kernel 1: h = x @ W   (M=N nodes, K=256, N=128), fp32 SIMT tiled GEMM
//   BM=64, BN=128 (full FOUT), BK=32, 256 threads, each thread 8x4 outputs.
// ---------------------------------------------------------------------------
#define BM 64
#define BN 128
#define BK 32
#define AS_STRIDE 68   // BM + 4 pad

__global__ __launch_bounds__(256) void gemm_kernel(
    const float* __restrict__ x,   // [N, FIN]
    const float* __restrict__ W,   // [FIN, FOUT]
    float* __restrict__ h,         // [N, FOUT]
    int N)
{
    __shared__ float As[BK][AS_STRIDE];  // transposed x tile: As[k][m]
    __shared__ float Bs[BK][BN];         // W tile: Bs[k][n]

    const int tid = threadIdx.x;
    const int tx  = tid & 31;   // 0..31 -> column group (tx*4)
    const int ty  = tid >> 5;   // 0..7  -> row group (ty*8)
    const int bm  = blockIdx.x * BM;

    float acc[8][4];
#pragma unroll
    for (int i = 0; i < 8; i++)
#pragma unroll
        for (int j = 0; j < 4; j++) acc[i][j] = 0.f;

    for (int k0 = 0; k0 < FIN; k0 += BK) {
        // Load x tile (64 rows x 32 k) -> transposed into As.
#pragma unroll
        for (int f = tid; f < BM * BK / 4; f += 256) {
            int r  = f >> 3;      // row in tile 0..63
            int c4 = f & 7;       // float4 index within the 32-wide k slice
            int gr = bm + r;
            if (gr >= N) gr = N - 1;               // clamp (dup, stores guarded)
            float4 v = *(const float4*)&x[(size_t)gr * FIN + k0 + c4 * 4];
            As[c4 * 4 + 0][r] = v.x;
            As[c4 * 4 + 1][r] = v.y;
            As[c4 * 4 + 2][r] = v.z;
            As[c4 * 4 + 3][r] = v.w;
        }
        // Load W tile (32 k x 128 n): 1024 float4, 4 per thread, coalesced.
#pragma unroll
        for (int f = tid; f < BK * BN / 4; f += 256) {
            int r  = f >> 5;
            int c4 = f & 31;
            *(float4*)&Bs[r][c4 * 4] =
                *(const float4*)&W[(size_t)(k0 + r) * FOUT + c4 * 4];
        }
        __syncthreads();

#pragma unroll
        for (int kk = 0; kk < BK; kk++) {
            float4 a0 = *(const float4*)&As[kk][ty * 8];      // broadcast
            float4 a1 = *(const float4*)&As[kk][ty * 8 + 4];  // broadcast
            float4 b  = *(const float4*)&Bs[kk][tx * 4];
            float av[8] = {a0.x, a0.y, a0.z, a0.w, a1.x, a1.y, a1.z, a1.w};
#pragma unroll
            for (int i = 0; i < 8; i++) {
                acc[i][0] = fmaf(av[i], b.x, acc[i][0]);
                acc[i][1] = fmaf(av[i], b.y, acc[i][1]);
                acc[i][2] = fmaf(av[i], b.z, acc[i][2]);
                acc[i][3] = fmaf(av[i], b.w, acc[i][3]);
            }
        }
        __syncthreads();
    }

#pragma unroll
    for (int i = 0; i < 8; i++) {
        int row = bm + ty * 8 + i;
        if (row < N) {
            float4 v = make_float4(acc[i][0], acc[i][1], acc[i][2], acc[i][3]);
            *(float4*)&h[(size_t)row * FOUT + tx * 4] = v;
        }
    }
}

// ---------------------------------------------------------------------------
// Kernel 2: scatter-add  out[row] += h[col]  for every edge.
//   One warp per edge; lane l owns columns [4l, 4l+4); vector float4 RED.
//   softmax over a size-1 axis == 1.0, so attention weights vanish.
//   NOTE: edge_index is int32 (JAX x64 disabled -> int64 request degrades).
// ---------------------------------------------------------------------------
__global__ __launch_bounds__(256) void scatter_kernel(
    const int* __restrict__ ei,   // [2, E] int32: row = ei[e], col = ei[E+e]
    const float* __restrict__ h,
    float* __restrict__ out,
    int E)
{
    int gw   = (blockIdx.x * blockDim.x + threadIdx.x) >> 5;  // global warp = edge
    int lane = threadIdx.x & 31;
    if (gw >= E) return;

    int row = __ldg(&ei[gw]);
    int col = __ldg(&ei[E + gw]);

    float4 v = *(const float4*)&h[(size_t)col * FOUT + lane * 4];
    atomicAdd((float4*)&out[(size_t)row * FOUT + lane * 4], v);
}

// ---------------------------------------------------------------------------
// Kernel 3: ELU in place.  elu(x) = x > 0 ? x : exp(x) - 1
// ---------------------------------------------------------------------------
__global__ void elu_kernel(float4* __restrict__ out, int n4) {
    int i = blockIdx.x * blockDim.x + threadIdx.x;
    if (i >= n4) return;
    float4 v = out[i];
    v.x = v.x > 0.f ? v.x : (expf(v.x) - 1.f);
    v.y = v.y > 0.f ? v.y : (expf(v.y) - 1.f);
    v.z = v.z > 0.f ? v.z : (expf(v.z) - 1.f);
    v.w = v.w > 0.f ? v.w : (expf(v.w) - 1.f);
    out[i] = v;
}

// ---------------------------------------------------------------------------
// Launch
//   inputs: d_in[0]=x [N,256] f32, d_in[1]=edge_index [2,E] i32,
//           d_in[2]=W [256,128] f32, d_in[3]=a [256,1] f32 (DEAD: softmax==1)
//   output: d_out [N,128] f32
// ---------------------------------------------------------------------------
extern "C" void kernel_launch(void* const* d_in, const int* in_sizes, int n_in,
                              void* d_out, int out_size)
{
    const float* x   = (const float*)d_in[0];
    const int*   ei  = (const int*)d_in[1];
    const float* W   = (const float*)d_in[2];
    float*       out = (float*)d_out;

    const int N = in_sizes[0] / FIN;     // 100000
    const int E = in_sizes[1] / 2;       // 1600000

    float* h;
    cudaGetSymbolAddress((void**)&h, g_h);

    // 0) zero accumulator (must happen every launch for graph replay)
    {
        int n4 = out_size / 4;
        zero_kernel<<<(n4 + 255) / 256, 256>>>((float4*)out, n4);
    }
    // 1) h = x @ W
    {
        int grid = (N + BM - 1) / BM;
        gemm_kernel<<<grid, 256>>>(x, W, h, N);
    }
    // 2) out[row] += h[col]
    {
        int blocks = (E + 7) / 8;          // 8 warps (edges) / block
        scatter_kernel<<<blocks, 256>>>(ei, h, out, E);
    }
    // 3) elu in place
    {
        int n4 = out_size / 4;
        elu_kernel<<<(n4 + 255) / 256, 256>>>((float4*)out, n4);
    }
}

// round 4
// speedup vs baseline: 1.0005x; 1.0005x over previous
#include <cuda_runtime.h>

// Problem constants (shapes fixed by the dataset)
#define FIN   256
#define FOUT  128
#define N_MAX 100000

// 51.2 MB scratch for h = x @ W   (allocation-free: __device__ global)
__device__ float g_h[(size_t)N_MAX * FOUT];

// ---------------------------------------------------------------------------
// Kernel 0: zero the output accumulator (d_out is poisoned / stale on replay)
// ---------------------------------------------------------------------------
__global__ void zero_kernel(float4* __restrict__ out, int n4) {
    int i = blockIdx.x * blockDim.x + threadIdx.x;
    if (i < n4) out[i] = make_float4(0.f, 0.f, 0.f, 0.f);
}

// ---------------------------------------------------------------------------
// Kernel 1: h = x @ W   (M=N nodes, K=256, N=128), fp32 SIMT tiled GEMM
//   BM=64, BN=128 (full FOUT), BK=32, 256 threads, each thread 8x4 outputs.
// ---------------------------------------------------------------------------
#define BM 64
#define BN 128
#define BK 32
#define AS_STRIDE 68   // BM + 4 pad

__global__ __launch_bounds__(256) void gemm_kernel(
    const float* __restrict__ x,   // [N, FIN]
    const float* __restrict__ W,   // [FIN, FOUT]
    float* __restrict__ h,         // [N, FOUT]
    int N)
{
    __shared__ float As[BK][AS_STRIDE];  // transposed x tile: As[k][m]
    __shared__ float Bs[BK][BN];         // W tile: Bs[k][n]

    const int tid = threadIdx.x;
    const int tx  = tid & 31;   // 0..31 -> column group (tx*4)
    const int ty  = tid >> 5;   // 0..7  -> row group (ty*8)
    const int bm  = blockIdx.x * BM;

    float acc[8][4];
#pragma unroll
    for (int i = 0; i < 8; i++)
#pragma unroll
        for (int j = 0; j < 4; j++) acc[i][j] = 0.f;

    for (int k0 = 0; k0 < FIN; k0 += BK) {
        // Load x tile (64 rows x 32 k) -> transposed into As.
#pragma unroll
        for (int f = tid; f < BM * BK / 4; f += 256) {
            int r  = f >> 3;      // row in tile 0..63
            int c4 = f & 7;       // float4 index within the 32-wide k slice
            int gr = bm + r;
            if (gr >= N) gr = N - 1;               // clamp (dup, stores guarded)
            float4 v = *(const float4*)&x[(size_t)gr * FIN + k0 + c4 * 4];
            As[c4 * 4 + 0][r] = v.x;
            As[c4 * 4 + 1][r] = v.y;
            As[c4 * 4 + 2][r] = v.z;
            As[c4 * 4 + 3][r] = v.w;
        }
        // Load W tile (32 k x 128 n): 1024 float4, 4 per thread, coalesced.
#pragma unroll
        for (int f = tid; f < BK * BN / 4; f += 256) {
            int r  = f >> 5;
            int c4 = f & 31;
            *(float4*)&Bs[r][c4 * 4] =
                *(const float4*)&W[(size_t)(k0 + r) * FOUT + c4 * 4];
        }
        __syncthreads();

#pragma unroll
        for (int kk = 0; kk < BK; kk++) {
            float4 a0 = *(const float4*)&As[kk][ty * 8];      // broadcast
            float4 a1 = *(const float4*)&As[kk][ty * 8 + 4];  // broadcast
            float4 b  = *(const float4*)&Bs[kk][tx * 4];
            float av[8] = {a0.x, a0.y, a0.z, a0.w, a1.x, a1.y, a1.z, a1.w};
#pragma unroll
            for (int i = 0; i < 8; i++) {
                acc[i][0] = fmaf(av[i], b.x, acc[i][0]);
                acc[i][1] = fmaf(av[i], b.y, acc[i][1]);
                acc[i][2] = fmaf(av[i], b.z, acc[i][2]);
                acc[i][3] = fmaf(av[i], b.w, acc[i][3]);
            }
        }
        __syncthreads();
    }

#pragma unroll
    for (int i = 0; i < 8; i++) {
        int row = bm + ty * 8 + i;
        if (row < N) {
            float4 v = make_float4(acc[i][0], acc[i][1], acc[i][2], acc[i][3]);
            *(float4*)&h[(size_t)row * FOUT + tx * 4] = v;
        }
    }
}

// ---------------------------------------------------------------------------
// Kernel 2: scatter-add  out[row] += h[col]  for every edge.
//   One warp per edge; lane l owns columns [4l, 4l+4); vector float4 RED.
//   softmax over a size-1 axis == 1.0, so attention weights vanish.
//   NOTE: edge_index is int32 (JAX x64 disabled -> int64 request degrades).
// ---------------------------------------------------------------------------
__global__ __launch_bounds__(256) void scatter_kernel(
    const int* __restrict__ ei,   // [2, E] int32: row = ei[e], col = ei[E+e]
    const float* __restrict__ h,
    float* __restrict__ out,
    int E)
{
    int gw   = (blockIdx.x * blockDim.x + threadIdx.x) >> 5;  // global warp = edge
    int lane = threadIdx.x & 31;
    if (gw >= E) return;

    int row = __ldg(&ei[gw]);
    int col = __ldg(&ei[E + gw]);

    float4 v = *(const float4*)&h[(size_t)col * FOUT + lane * 4];
    atomicAdd((float4*)&out[(size_t)row * FOUT + lane * 4], v);
}

// ---------------------------------------------------------------------------
// Kernel 3: ELU in place.  elu(x) = x > 0 ? x : exp(x) - 1
// ---------------------------------------------------------------------------
__global__ void elu_kernel(float4* __restrict__ out, int n4) {
    int i = blockIdx.x * blockDim.x + threadIdx.x;
    if (i >= n4) return;
    float4 v = out[i];
    v.x = v.x > 0.f ? v.x : (expf(v.x) - 1.f);
    v.y = v.y > 0.f ? v.y : (expf(v.y) - 1.f);
    v.z = v.z > 0.f ? v.z : (expf(v.z) - 1.f);
    v.w = v.w > 0.f ? v.w : (expf(v.w) - 1.f);
    out[i] = v;
}

// ---------------------------------------------------------------------------
// Launch
//   inputs: d_in[0]=x [N,256] f32, d_in[1]=edge_index [2,E] i32,
//           d_in[2]=W [256,128] f32, d_in[3]=a [256,1] f32 (DEAD: softmax==1)
//   output: d_out [N,128] f32
// ---------------------------------------------------------------------------
extern "C" void kernel_launch(void* const* d_in, const int* in_sizes, int n_in,
                              void* d_out, int out_size)
{
    const float* x   = (const float*)d_in[0];
    const int*   ei  = (const int*)d_in[1];
    const float* W   = (const float*)d_in[2];
    float*       out = (float*)d_out;

    const int N = in_sizes[0] / FIN;     // 100000
    const int E = in_sizes[1] / 2;       // 1600000

    float* h;
    cudaGetSymbolAddress((void**)&h, g_h);

    // 0) zero accumulator (must happen every launch for graph replay)
    {
        int n4 = out_size / 4;
        zero_kernel<<<(n4 + 255) / 256, 256>>>((float4*)out, n4);
    }
    // 1) h = x @ W
    {
        int grid = (N + BM - 1) / BM;
        gemm_kernel<<<grid, 256>>>(x, W, h, N);
    }
    // 2) out[row] += h[col]
    {
        int blocks = (E + 7) / 8;          // 8 warps (edges) / block
        scatter_kernel<<<blocks, 256>>>(ei, h, out, E);
    }
    // 3) elu in place
    {
        int n4 = out_size / 4;
        elu_kernel<<<(n4 + 255) / 256, 256>>>((float4*)out, n4);
    }
}